// round 1
// baseline (speedup 1.0000x reference)
#include <cuda_runtime.h>

// Problem constants: B=256 images/texts, m=128 tokens, d=768 dim
#define TEMPERATURE 0.07f
constexpr int BSZ  = 256;
constexpr int MTOK = 128;
constexpr int DDIM = 768;
constexpr int KB   = 16;   // K block per shared-memory stage

// Scratch (device globals — no allocation allowed in kernel_launch)
__device__ float g_S[BSZ * BSZ];        // max-sim matrix (un-scaled dots)
__device__ float g_partial[BSZ];        // per-index partial losses

// ---------------------------------------------------------------------------
// Kernel 1: fused GEMM + max over m.
// Grid: (2, 256). blockIdx.x selects 128 i-rows, blockIdx.y = j (one text).
// CTA computes the 128x128 tile C[i, m] = V[i,:] . T[j,m,:], then reduces
// max over the 128 m-columns and writes S[i][j].
// Thread layout: 256 threads, tx = tid&15 owns columns {tx*4..+3, 64+tx*4..+3},
// ty = tid>>4 owns rows {ty*4..+3, 64+ty*4..+3}  (4+4 split => conflict-free
// LDS.128: 16 lanes at stride 16B cover 256B contiguous, 2 phases, 0 conflicts).
// ---------------------------------------------------------------------------
__global__ __launch_bounds__(256, 2)
void gemm_max_kernel(const float* __restrict__ V, const float* __restrict__ T) {
    __shared__ float As[KB][132];   // transposed: As[k][i-row]
    __shared__ float Bs[KB][132];   // transposed: Bs[k][m-col]

    const int i0  = blockIdx.x * 128;
    const int j   = blockIdx.y;
    const float* __restrict__ Bbase = T + (size_t)j * MTOK * DDIM;

    const int tid = threadIdx.x;
    const int tx  = tid & 15;
    const int ty  = tid >> 4;

    float acc[8][8];
#pragma unroll
    for (int r = 0; r < 8; r++)
#pragma unroll
        for (int c = 0; c < 8; c++) acc[r][c] = 0.0f;

    for (int k0 = 0; k0 < DDIM; k0 += KB) {
        // Stage A (128 rows x 16 k) and B (128 rows x 16 k): 512 float4 each,
        // 2 float4 per thread per matrix, stored transposed into smem.
#pragma unroll
        for (int u = 0; u < 2; u++) {
            const int f   = tid + u * 256;
            const int row = f >> 2;
            const int kq  = (f & 3) << 2;
            float4 a = *(const float4*)(V + (size_t)(i0 + row) * DDIM + k0 + kq);
            As[kq + 0][row] = a.x; As[kq + 1][row] = a.y;
            As[kq + 2][row] = a.z; As[kq + 3][row] = a.w;
            float4 b = *(const float4*)(Bbase + (size_t)row * DDIM + k0 + kq);
            Bs[kq + 0][row] = b.x; Bs[kq + 1][row] = b.y;
            Bs[kq + 2][row] = b.z; Bs[kq + 3][row] = b.w;
        }
        __syncthreads();

#pragma unroll
        for (int kk = 0; kk < KB; kk++) {
            float ra[8], rb[8];
            *(float4*)(ra    ) = *(const float4*)&As[kk][ty * 4];
            *(float4*)(ra + 4) = *(const float4*)&As[kk][64 + ty * 4];
            *(float4*)(rb    ) = *(const float4*)&Bs[kk][tx * 4];
            *(float4*)(rb + 4) = *(const float4*)&Bs[kk][64 + tx * 4];
#pragma unroll
            for (int r = 0; r < 8; r++)
#pragma unroll
                for (int c = 0; c < 8; c++)
                    acc[r][c] = fmaf(ra[r], rb[c], acc[r][c]);
        }
        __syncthreads();
    }

    // Epilogue: max over the 128 m columns per i-row.
    // Local max over this thread's 8 columns, then shfl-xor reduce across the
    // 16-lane tx group (xor masks 1,2,4,8 only touch bits 0-3 = tx).
#pragma unroll
    for (int r = 0; r < 8; r++) {
        float mx = acc[r][0];
#pragma unroll
        for (int c = 1; c < 8; c++) mx = fmaxf(mx, acc[r][c]);
#pragma unroll
        for (int s = 8; s >= 1; s >>= 1)
            mx = fmaxf(mx, __shfl_xor_sync(0xffffffffu, mx, s));
        if (tx == 0) {
            const int row = (r < 4) ? (ty * 4 + r) : (64 + ty * 4 + (r - 4));
            g_S[(size_t)(i0 + row) * BSZ + j] = mx;
        }
    }
}

// ---------------------------------------------------------------------------
// Kernel 2: per-index i, compute (LSE_row_i - L_ii) + (LSE_col_i - L_ii),
// where L = S / TEMP, with max-subtraction for stability (|L| can reach ~1e3).
// ---------------------------------------------------------------------------
__global__ void lse_kernel() {
    __shared__ float sm[BSZ];
    const int i = blockIdx.x;
    const int t = threadIdx.x;

    const float rv   = g_S[(size_t)i * BSZ + t];
    const float cv   = g_S[(size_t)t * BSZ + i];
    const float diag = g_S[(size_t)i * BSZ + i] * (1.0f / TEMPERATURE);

    // ---- row LSE ----
    sm[t] = rv; __syncthreads();
    for (int s = 128; s >= 1; s >>= 1) {
        if (t < s) sm[t] = fmaxf(sm[t], sm[t + s]);
        __syncthreads();
    }
    const float rmax = sm[0]; __syncthreads();
    sm[t] = expf((rv - rmax) * (1.0f / TEMPERATURE)); __syncthreads();
    for (int s = 128; s >= 1; s >>= 1) {
        if (t < s) sm[t] += sm[t + s];
        __syncthreads();
    }
    const float rsum = sm[0]; __syncthreads();

    // ---- col LSE ----
    sm[t] = cv; __syncthreads();
    for (int s = 128; s >= 1; s >>= 1) {
        if (t < s) sm[t] = fmaxf(sm[t], sm[t + s]);
        __syncthreads();
    }
    const float cmax = sm[0]; __syncthreads();
    sm[t] = expf((cv - cmax) * (1.0f / TEMPERATURE)); __syncthreads();
    for (int s = 128; s >= 1; s >>= 1) {
        if (t < s) sm[t] += sm[t + s];
        __syncthreads();
    }
    const float csum = sm[0];

    if (t == 0) {
        const float lse_r = rmax * (1.0f / TEMPERATURE) + logf(rsum);
        const float lse_c = cmax * (1.0f / TEMPERATURE) + logf(csum);
        g_partial[i] = (lse_r - diag) + (lse_c - diag);
    }
}

// ---------------------------------------------------------------------------
// Kernel 3: final reduction over 256 partials -> scalar loss.
// loss = (mean_i row_term + mean_i col_term) / 2 = sum(partial) / (2*B)
// ---------------------------------------------------------------------------
__global__ void finalize_kernel(float* __restrict__ out) {
    __shared__ float sm[BSZ];
    const int t = threadIdx.x;
    sm[t] = g_partial[t]; __syncthreads();
    for (int s = 128; s >= 1; s >>= 1) {
        if (t < s) sm[t] += sm[t + s];
        __syncthreads();
    }
    if (t == 0) out[0] = sm[0] * (1.0f / (2.0f * (float)BSZ));
}

// ---------------------------------------------------------------------------
extern "C" void kernel_launch(void* const* d_in, const int* in_sizes, int n_in,
                              void* d_out, int out_size) {
    const float* V = (const float*)d_in[0];  // v_final [256, 768]
    const float* T = (const float*)d_in[1];  // T_fused [256, 128, 768]
    float* out = (float*)d_out;

    dim3 grid(2, BSZ);
    gemm_max_kernel<<<grid, 256>>>(V, T);
    lse_kernel<<<BSZ, BSZ>>>();
    finalize_kernel<<<1, BSZ>>>(out);
}

// round 3
// speedup vs baseline: 2.3900x; 2.3900x over previous
#include <cuda_runtime.h>
#include <cuda_bf16.h>
#include <cstdint>

#define TEMPERATURE 0.07f
constexpr int BSZ  = 256;
constexpr int MTOK = 128;
constexpr int DDIM = 768;

constexpr int KC     = 64;                 // K elements per smem stage (bf16)
constexpr int NCHUNK = DDIM / KC;          // 12
constexpr int PB     = 144;                // smem row pitch bytes (128 data + 16 pad)
constexpr int TILE_B = 128 * PB;           // 18432 bytes per tile
constexpr int STAGE_B = 4 * TILE_B;        // Ahi, Alo, Bhi, Blo
constexpr int SMEM_TOTAL = 2 * STAGE_B;    // 147456 (double buffered)

// Scratch device globals (no allocation allowed anywhere)
__device__ float g_S[BSZ * BSZ];
__device__ float g_partial[BSZ];
__device__ __align__(16) __nv_bfloat16 g_Ahi[BSZ * DDIM];
__device__ __align__(16) __nv_bfloat16 g_Alo[BSZ * DDIM];

// ---------------------------------------------------------------------------
__device__ __forceinline__ uint32_t smem_u32(const void* p) {
    uint32_t a;
    asm("{ .reg .u64 t; cvta.to.shared.u64 t, %1; cvt.u32.u64 %0, t; }"
        : "=r"(a) : "l"(p));
    return a;
}
__device__ __forceinline__ void ldsm_x4(uint32_t* r, uint32_t addr) {
    asm volatile("ldmatrix.sync.aligned.m8n8.x4.shared.b16 {%0,%1,%2,%3}, [%4];"
                 : "=r"(r[0]), "=r"(r[1]), "=r"(r[2]), "=r"(r[3]) : "r"(addr));
}
__device__ __forceinline__ void mma_bf16(float* d, const uint32_t* a,
                                         const uint32_t* b) {
    asm volatile(
        "mma.sync.aligned.m16n8k16.row.col.f32.bf16.bf16.f32 "
        "{%0,%1,%2,%3}, {%4,%5,%6,%7}, {%8,%9}, {%0,%1,%2,%3};"
        : "+f"(d[0]), "+f"(d[1]), "+f"(d[2]), "+f"(d[3])
        : "r"(a[0]), "r"(a[1]), "r"(a[2]), "r"(a[3]), "r"(b[0]), "r"(b[1]));
}

// ---------------------------------------------------------------------------
// Kernel 0: split V (fp32) into bf16 hi/lo once.
// ---------------------------------------------------------------------------
__global__ void convert_a_kernel(const float* __restrict__ V) {
    int idx = blockIdx.x * blockDim.x + threadIdx.x;
    if (idx < BSZ * DDIM) {
        float x = V[idx];
        __nv_bfloat16 h = __float2bfloat16_rn(x);
        g_Ahi[idx] = h;
        g_Alo[idx] = __float2bfloat16_rn(x - __bfloat162float(h));
    }
}

// ---------------------------------------------------------------------------
// Kernel 1: split-bf16 mma.sync GEMM + fused max over m.
// Grid (2, 256): x = i-half (rows i0..i0+127), y = j.  8 warps: 4(M) x 2(N),
// warp tile 32x64, m16n8k16 bf16 HMMA, fp32 accum. Double-buffered smem,
// LDG->reg prefetch of next K chunk overlaps HMMA of current chunk.
// ---------------------------------------------------------------------------
__global__ __launch_bounds__(256, 1)
void gemm_max_mma(const float* __restrict__ T) {
    extern __shared__ char smem[];
    const uint32_t sbase = smem_u32(smem);
    const int tid  = threadIdx.x;
    const int lane = tid & 31;
    const int wid  = tid >> 5;
    const int warp_m = wid & 3;
    const int warp_n = wid >> 2;

    const int i0 = blockIdx.x * 128;
    const int j  = blockIdx.y;
    const float* __restrict__ Tj = T + (size_t)j * MTOK * DDIM;

    float acc[2][8][4];
#pragma unroll
    for (int mt = 0; mt < 2; mt++)
#pragma unroll
        for (int nt = 0; nt < 8; nt++)
#pragma unroll
            for (int e = 0; e < 4; e++) acc[mt][nt][e] = 0.0f;

    // ldmatrix lane offsets (tile-relative, bytes)
    const int q   = lane >> 3;
    const int idx = lane & 7;
    // A x4: quads -> (m0-7,k0-7),(m8-15,k0-7),(m0-7,k8-15),(m8-15,k8-15)
    const uint32_t a_off = (uint32_t)((warp_m * 32 + ((q & 1) * 8 + idx)) * PB
                                      + (q >> 1) * 16);
    // B x4: quads -> (n0-7,k0-7),(n0-7,k8-15),(n8-15,k0-7),(n8-15,k8-15)
    const uint32_t b_off = (uint32_t)((warp_n * 64 + ((q >> 1) * 8 + idx)) * PB
                                      + (q & 1) * 16);

    float4 br[8];   // B prefetch (fp32)
    uint4  ar[8];   // A prefetch (bf16 hi:0-3, lo:4-7)

    // ---- helpers as local lambdas -----------------------------------------
    auto ldg_chunk = [&](int k0) {
#pragma unroll
        for (int p = 0; p < 8; p++) {
            const int u = p * 256 + tid;
            br[p] = *(const float4*)(Tj + (size_t)(u >> 4) * DDIM + k0 + (u & 15) * 4);
        }
#pragma unroll
        for (int p = 0; p < 4; p++) {
            const int u = p * 256 + tid;
            const int row = u >> 3, kc = (u & 7) * 8;
            const size_t g = (size_t)(i0 + row) * DDIM + k0 + kc;
            ar[p]     = *(const uint4*)(g_Ahi + g);
            ar[p + 4] = *(const uint4*)(g_Alo + g);
        }
    };
    auto sts_chunk = [&](char* stage) {
        char* sAhi = stage;
        char* sAlo = stage + TILE_B;
        char* sBhi = stage + 2 * TILE_B;
        char* sBlo = stage + 3 * TILE_B;
#pragma unroll
        for (int p = 0; p < 8; p++) {
            const int u = p * 256 + tid;
            const int row = u >> 4, kq = (u & 15) * 4;
            const float4 b = br[p];
            __nv_bfloat162 h01 = __floats2bfloat162_rn(b.x, b.y);
            __nv_bfloat162 h23 = __floats2bfloat162_rn(b.z, b.w);
            __nv_bfloat162 l01 = __floats2bfloat162_rn(b.x - __bfloat162float(h01.x),
                                                       b.y - __bfloat162float(h01.y));
            __nv_bfloat162 l23 = __floats2bfloat162_rn(b.z - __bfloat162float(h23.x),
                                                       b.w - __bfloat162float(h23.y));
            const uint32_t o = (uint32_t)(row * PB + kq * 2);
            *(uint2*)(sBhi + o) = make_uint2(*reinterpret_cast<unsigned*>(&h01),
                                             *reinterpret_cast<unsigned*>(&h23));
            *(uint2*)(sBlo + o) = make_uint2(*reinterpret_cast<unsigned*>(&l01),
                                             *reinterpret_cast<unsigned*>(&l23));
        }
#pragma unroll
        for (int p = 0; p < 4; p++) {
            const int u = p * 256 + tid;
            const int row = u >> 3, kc = (u & 7) * 8;
            const uint32_t o = (uint32_t)(row * PB + kc * 2);
            *(uint4*)(sAhi + o) = ar[p];
            *(uint4*)(sAlo + o) = ar[p + 4];
        }
    };
    auto compute_chunk = [&](uint32_t sstage) {
#pragma unroll
        for (int ks = 0; ks < KC / 16; ks++) {
            uint32_t ah[2][4], al[2][4];
#pragma unroll
            for (int mt = 0; mt < 2; mt++) {
                ldsm_x4(ah[mt], sstage + 0 * TILE_B + a_off + mt * 16 * PB + ks * 32);
                ldsm_x4(al[mt], sstage + 1 * TILE_B + a_off + mt * 16 * PB + ks * 32);
            }
#pragma unroll
            for (int np = 0; np < 4; np++) {
                uint32_t bh[4], bl[4];
                ldsm_x4(bh, sstage + 2 * TILE_B + b_off + np * 16 * PB + ks * 32);
                ldsm_x4(bl, sstage + 3 * TILE_B + b_off + np * 16 * PB + ks * 32);
#pragma unroll
                for (int mt = 0; mt < 2; mt++) {
                    mma_bf16(acc[mt][2 * np],     ah[mt], bh);
                    mma_bf16(acc[mt][2 * np],     ah[mt], bl);
                    mma_bf16(acc[mt][2 * np],     al[mt], bh);
                    mma_bf16(acc[mt][2 * np + 1], ah[mt], bh + 2);
                    mma_bf16(acc[mt][2 * np + 1], ah[mt], bl + 2);
                    mma_bf16(acc[mt][2 * np + 1], al[mt], bh + 2);
                }
            }
        }
    };
    // -----------------------------------------------------------------------

    // Prologue: fill stage 0 with chunk 0.
    ldg_chunk(0);
    sts_chunk(smem);
    __syncthreads();

    for (int c = 0; c < NCHUNK; c++) {
        const int s = c & 1;
        if (c + 1 < NCHUNK) ldg_chunk((c + 1) * KC);     // prefetch next chunk
        compute_chunk(sbase + s * STAGE_B);              // HMMA on current
        if (c + 1 < NCHUNK) sts_chunk(smem + (1 - s) * STAGE_B);
        __syncthreads();
    }

    // Epilogue: max over the 128 m columns per i-row.
    // accum mapping: c0,c1 -> row (L>>2), cols 2(L&3)+{0,1}; c2,c3 -> row+8.
    float* buf = (float*)smem;   // [128][2] partial per-row maxes
#pragma unroll
    for (int mt = 0; mt < 2; mt++) {
        float mlo = -3.402823466e+38f, mhi = -3.402823466e+38f;
#pragma unroll
        for (int nt = 0; nt < 8; nt++) {
            mlo = fmaxf(mlo, fmaxf(acc[mt][nt][0], acc[mt][nt][1]));
            mhi = fmaxf(mhi, fmaxf(acc[mt][nt][2], acc[mt][nt][3]));
        }
        mlo = fmaxf(mlo, __shfl_xor_sync(0xffffffffu, mlo, 1));
        mlo = fmaxf(mlo, __shfl_xor_sync(0xffffffffu, mlo, 2));
        mhi = fmaxf(mhi, __shfl_xor_sync(0xffffffffu, mhi, 1));
        mhi = fmaxf(mhi, __shfl_xor_sync(0xffffffffu, mhi, 2));
        if ((lane & 3) == 0) {
            const int row = warp_m * 32 + mt * 16 + (lane >> 2);
            buf[row * 2 + warp_n]       = mlo;
            buf[(row + 8) * 2 + warp_n] = mhi;
        }
    }
    __syncthreads();
    if (tid < 128)
        g_S[(size_t)(i0 + tid) * BSZ + j] = fmaxf(buf[tid * 2], buf[tid * 2 + 1]);
}

// ---------------------------------------------------------------------------
// Kernel 2: per-index i, (LSE_row - diag) + (LSE_col - diag), stabilized.
// ---------------------------------------------------------------------------
__global__ void lse_kernel() {
    __shared__ float sm[BSZ];
    const int i = blockIdx.x;
    const int t = threadIdx.x;

    const float rv   = g_S[(size_t)i * BSZ + t];
    const float cv   = g_S[(size_t)t * BSZ + i];
    const float diag = g_S[(size_t)i * BSZ + i] * (1.0f / TEMPERATURE);

    sm[t] = rv; __syncthreads();
    for (int s = 128; s >= 1; s >>= 1) {
        if (t < s) sm[t] = fmaxf(sm[t], sm[t + s]);
        __syncthreads();
    }
    const float rmax = sm[0]; __syncthreads();
    sm[t] = expf((rv - rmax) * (1.0f / TEMPERATURE)); __syncthreads();
    for (int s = 128; s >= 1; s >>= 1) {
        if (t < s) sm[t] += sm[t + s];
        __syncthreads();
    }
    const float rsum = sm[0]; __syncthreads();

    sm[t] = cv; __syncthreads();
    for (int s = 128; s >= 1; s >>= 1) {
        if (t < s) sm[t] = fmaxf(sm[t], sm[t + s]);
        __syncthreads();
    }
    const float cmax = sm[0]; __syncthreads();
    sm[t] = expf((cv - cmax) * (1.0f / TEMPERATURE)); __syncthreads();
    for (int s = 128; s >= 1; s >>= 1) {
        if (t < s) sm[t] += sm[t + s];
        __syncthreads();
    }
    const float csum = sm[0];

    if (t == 0) {
        const float lse_r = rmax * (1.0f / TEMPERATURE) + logf(rsum);
        const float lse_c = cmax * (1.0f / TEMPERATURE) + logf(csum);
        g_partial[i] = (lse_r - diag) + (lse_c - diag);
    }
}

__global__ void finalize_kernel(float* __restrict__ out) {
    __shared__ float sm[BSZ];
    const int t = threadIdx.x;
    sm[t] = g_partial[t]; __syncthreads();
    for (int s = 128; s >= 1; s >>= 1) {
        if (t < s) sm[t] += sm[t + s];
        __syncthreads();
    }
    if (t == 0) out[0] = sm[0] * (1.0f / (2.0f * (float)BSZ));
}

// ---------------------------------------------------------------------------
extern "C" void kernel_launch(void* const* d_in, const int* in_sizes, int n_in,
                              void* d_out, int out_size) {
    const float* V = (const float*)d_in[0];  // v_final [256, 768]
    const float* T = (const float*)d_in[1];  // T_fused [256, 128, 768]
    float* out = (float*)d_out;

    cudaFuncSetAttribute(gemm_max_mma, cudaFuncAttributeMaxDynamicSharedMemorySize,
                         SMEM_TOTAL);

    convert_a_kernel<<<(BSZ * DDIM + 255) / 256, 256>>>(V);
    gemm_max_mma<<<dim3(2, BSZ), 256, SMEM_TOTAL>>>(T);
    lse_kernel<<<BSZ, BSZ>>>();
    finalize_kernel<<<1, BSZ>>>(out);
}